// round 3
// baseline (speedup 1.0000x reference)
#include <cuda_runtime.h>
#include <math.h>

#define NB 2
#define NT 2048
#define NC 768
#define NH 12
#define ND 64

// Scratch (allocation-free rule: device globals)
__device__ float g_q[NB*NH*NT*ND];   // [b][h][t][d]
__device__ float g_k[NB*NH*NT*ND];
__device__ float g_v[NB*NH*NT*ND];
__device__ float g_y[NB*NT*NC];      // [b][t][c]

// ---------------------------------------------------------------------------
// NT GEMM: C[m,n] = sum_k A[m,k] * B[n,k]
// BM=BN=128, BK=32, 256 threads, 8x8 per-thread microtile.
// MODE 0: A=x, scatter epilogue into g_q/g_k/g_v ([b,h,t,d] layout)
// MODE 1: A=g_y (device global), plain row-major C write
// ---------------------------------------------------------------------------
template<int MODE>
__launch_bounds__(256)
__global__ void gemm_nt(const float* __restrict__ Aext,
                        const float* __restrict__ Bw,
                        float* __restrict__ Cout,
                        int K, int N)
{
    const float* A = (MODE == 0) ? Aext : g_y;

    __shared__ __align__(16) float As[32 * 132];  // As[kk][m], stride 132
    __shared__ __align__(16) float Bs[32 * 132];  // Bs[kk][n]

    const int m0 = blockIdx.y * 128;
    const int n0 = blockIdx.x * 128;
    const int tid = threadIdx.x;
    const int tx = tid & 15;   // n-dim group (16)
    const int ty = tid >> 4;   // m-dim group (16)

    float acc[8][8];
    #pragma unroll
    for (int i = 0; i < 8; i++)
        #pragma unroll
        for (int j = 0; j < 8; j++)
            acc[i][j] = 0.0f;

    for (int k0 = 0; k0 < K; k0 += 32) {
        // Load 128x32 tiles of A and B, transposed into smem.
        #pragma unroll
        for (int i = 0; i < 4; i++) {
            int e = tid + i * 256;            // float4 index 0..1023
            int row = e >> 3;
            int c4 = (e & 7) << 2;            // 0,4,...,28
            float4 va = *(const float4*)(A + (size_t)(m0 + row) * K + k0 + c4);
            As[(c4 + 0) * 132 + row] = va.x;
            As[(c4 + 1) * 132 + row] = va.y;
            As[(c4 + 2) * 132 + row] = va.z;
            As[(c4 + 3) * 132 + row] = va.w;
            float4 vb = *(const float4*)(Bw + (size_t)(n0 + row) * K + k0 + c4);
            Bs[(c4 + 0) * 132 + row] = vb.x;
            Bs[(c4 + 1) * 132 + row] = vb.y;
            Bs[(c4 + 2) * 132 + row] = vb.z;
            Bs[(c4 + 3) * 132 + row] = vb.w;
        }
        __syncthreads();

        #pragma unroll 8
        for (int kk = 0; kk < 32; kk++) {
            float a[8], b[8];
            *(float4*)&a[0] = *(const float4*)(As + kk * 132 + ty * 8);
            *(float4*)&a[4] = *(const float4*)(As + kk * 132 + ty * 8 + 4);
            *(float4*)&b[0] = *(const float4*)(Bs + kk * 132 + tx * 8);
            *(float4*)&b[4] = *(const float4*)(Bs + kk * 132 + tx * 8 + 4);
            #pragma unroll
            for (int i = 0; i < 8; i++)
                #pragma unroll
                for (int j = 0; j < 8; j++)
                    acc[i][j] = fmaf(a[i], b[j], acc[i][j]);
        }
        __syncthreads();
    }

    if (MODE == 0) {
        // Scatter qkv into per-head q/k/v scratch.
        // Each 8-wide j-run is 8-aligned within a 64-aligned head slice, so
        // the whole run stays inside one (which, h) destination: vector-store.
        #pragma unroll
        for (int i = 0; i < 8; i++) {
            int m = m0 + ty * 8 + i;
            int b = m >> 11;          // /2048
            int t = m & 2047;
            int n = n0 + tx * 8;
            int which = n / NC;
            int r = n - which * NC;
            int h = r >> 6;
            int d = r & 63;
            float* dst = (which == 0) ? g_q : (which == 1) ? g_k : g_v;
            float* p = dst + (((size_t)b * NH + h) * NT + t) * ND + d;
            *(float4*)(p + 0) = *(const float4*)&acc[i][0];
            *(float4*)(p + 4) = *(const float4*)&acc[i][4];
        }
    } else {
        #pragma unroll
        for (int i = 0; i < 8; i++) {
            int m = m0 + ty * 8 + i;
            float* p = Cout + (size_t)m * N + n0 + tx * 8;
            *(float4*)(p + 0) = *(const float4*)&acc[i][0];
            *(float4*)(p + 4) = *(const float4*)&acc[i][4];
        }
    }
}

// ---------------------------------------------------------------------------
// Flash-style causal attention, fp32.
// Block: 128 threads (16 ty x 8 tx), Q tile = 128 rows, K/V tile = 64 keys.
// Per thread: 8 q-rows x 8 key-cols (S), 8 q-rows x 8 d-cols (O).
// P (probs) reuses K's smem buffer. Online softmax over K tiles.
// ---------------------------------------------------------------------------
#define Q_ELEMS (128 * 65)
#define KP_ELEMS (128 * 65)
#define V_ELEMS (64 * 64)
#define ATTN_SMEM ((Q_ELEMS + KP_ELEMS + V_ELEMS) * 4)

__launch_bounds__(128)
__global__ void attn_kernel()
{
    extern __shared__ __align__(16) float sm[];
    float* Qs = sm;                       // [128][65] row-major
    float* KP = sm + Q_ELEMS;             // K: [64][65] row-major, then P: [128][65]
    float* Vs = sm + Q_ELEMS + KP_ELEMS;  // [64][64] row-major

    // Reverse qt so heaviest (most K tiles) blocks launch first.
    const int qt = (int)gridDim.x - 1 - (int)blockIdx.x;   // 0..15
    const int bh = blockIdx.y;                             // 0..23
    const int b = bh / NH;
    const int h = bh - b * NH;
    const int tid = threadIdx.x;
    const int tx = tid & 7;
    const int ty = tid >> 3;

    const size_t head_base = ((size_t)b * NH + h) * (size_t)NT * ND;
    const int q0 = qt * 128;

    // Load Q tile (coalesced; conflict-free stores since stride 65)
    for (int e = tid; e < 128 * 64; e += 128) {
        int row = e >> 6, d = e & 63;
        Qs[row * 65 + d] = g_q[head_base + (size_t)(q0 + row) * ND + d];
    }

    float m_r[8], l_r[8], o[8][8];
    #pragma unroll
    for (int r = 0; r < 8; r++) {
        m_r[r] = -1e30f;
        l_r[r] = 0.0f;
        #pragma unroll
        for (int c = 0; c < 8; c++) o[r][c] = 0.0f;
    }

    const int kt_max = 2 * qt + 1;
    for (int kt = 0; kt <= kt_max; kt++) {
        const int k0 = kt * 64;

        __syncthreads();  // prev-iter readers of KP/Vs done (and Q load on iter 0)
        for (int e = tid; e < 64 * 64; e += 128) {
            int row = e >> 6, d = e & 63;
            float kvk = g_k[head_base + (size_t)(k0 + row) * ND + d];
            float kvv = g_v[head_base + (size_t)(k0 + row) * ND + d];
            KP[row * 65 + d] = kvk;
            Vs[row * 64 + d] = kvv;
        }
        __syncthreads();

        // S = Q K^T
        float s[8][8];
        #pragma unroll
        for (int r = 0; r < 8; r++)
            #pragma unroll
            for (int c = 0; c < 8; c++) s[r][c] = 0.0f;

        #pragma unroll 4
        for (int d = 0; d < 64; d++) {
            float qf[8], kf[8];
            #pragma unroll
            for (int r = 0; r < 8; r++) qf[r] = Qs[(ty * 8 + r) * 65 + d];
            #pragma unroll
            for (int c = 0; c < 8; c++) kf[c] = KP[(tx * 8 + c) * 65 + d];
            #pragma unroll
            for (int r = 0; r < 8; r++)
                #pragma unroll
                for (int c = 0; c < 8; c++)
                    s[r][c] = fmaf(qf[r], kf[c], s[r][c]);
        }

        // scale + causal mask
        const bool need_mask = (kt >= 2 * qt);
        #pragma unroll
        for (int r = 0; r < 8; r++) {
            int rg = q0 + ty * 8 + r;
            #pragma unroll
            for (int c = 0; c < 8; c++) {
                float v = s[r][c] * 0.125f;   // 1/sqrt(64)
                if (need_mask && (k0 + tx * 8 + c > rg)) v = -1e30f;
                s[r][c] = v;
            }
        }

        // online softmax update (row groups of 8 lanes: shfl.xor 1,2,4)
        #pragma unroll
        for (int r = 0; r < 8; r++) {
            float mx = s[r][0];
            #pragma unroll
            for (int c = 1; c < 8; c++) mx = fmaxf(mx, s[r][c]);
            mx = fmaxf(mx, __shfl_xor_sync(0xffffffffu, mx, 1));
            mx = fmaxf(mx, __shfl_xor_sync(0xffffffffu, mx, 2));
            mx = fmaxf(mx, __shfl_xor_sync(0xffffffffu, mx, 4));
            float mnew = fmaxf(m_r[r], mx);
            float alpha = __expf(m_r[r] - mnew);
            m_r[r] = mnew;
            float rs = 0.0f;
            #pragma unroll
            for (int c = 0; c < 8; c++) {
                float p = __expf(s[r][c] - mnew);
                s[r][c] = p;
                rs += p;
            }
            rs += __shfl_xor_sync(0xffffffffu, rs, 1);
            rs += __shfl_xor_sync(0xffffffffu, rs, 2);
            rs += __shfl_xor_sync(0xffffffffu, rs, 4);
            l_r[r] = l_r[r] * alpha + rs;
            #pragma unroll
            for (int c = 0; c < 8; c++) o[r][c] *= alpha;
        }

        __syncthreads();  // all reads of K (in KP) complete
        // write P into KP buffer
        #pragma unroll
        for (int r = 0; r < 8; r++)
            #pragma unroll
            for (int c = 0; c < 8; c++)
                KP[(ty * 8 + r) * 65 + tx * 8 + c] = s[r][c];
        __syncthreads();

        // O += P V
        #pragma unroll 4
        for (int k = 0; k < 64; k++) {
            float pf[8], vf[8];
            #pragma unroll
            for (int r = 0; r < 8; r++) pf[r] = KP[(ty * 8 + r) * 65 + k];
            *(float4*)&vf[0] = *(const float4*)(Vs + k * 64 + tx * 8);
            *(float4*)&vf[4] = *(const float4*)(Vs + k * 64 + tx * 8 + 4);
            #pragma unroll
            for (int r = 0; r < 8; r++)
                #pragma unroll
                for (int c = 0; c < 8; c++)
                    o[r][c] = fmaf(pf[r], vf[c], o[r][c]);
        }
    }

    // epilogue: normalize, write to [b,t,c] layout for proj GEMM
    #pragma unroll
    for (int r = 0; r < 8; r++) {
        float inv = 1.0f / l_r[r];
        int trow = q0 + ty * 8 + r;
        float* p = g_y + ((size_t)b * NT + trow) * NC + h * ND + tx * 8;
        float tmp[8];
        #pragma unroll
        for (int c = 0; c < 8; c++) tmp[c] = o[r][c] * inv;
        *(float4*)(p + 0) = *(const float4*)&tmp[0];
        *(float4*)(p + 4) = *(const float4*)&tmp[4];
    }
}

// ---------------------------------------------------------------------------
extern "C" void kernel_launch(void* const* d_in, const int* in_sizes, int n_in,
                              void* d_out, int out_size)
{
    // Defensive input identification by element count (all distinct)
    const float* x  = nullptr;   // 2*2048*768   = 3145728
    const float* Wa = nullptr;   // 2304*768     = 1769472
    const float* Wp = nullptr;   // 768*768      = 589824
    for (int i = 0; i < n_in; i++) {
        if (in_sizes[i] == NB * NT * NC)      x  = (const float*)d_in[i];
        else if (in_sizes[i] == 3 * NC * NC)  Wa = (const float*)d_in[i];
        else if (in_sizes[i] == NC * NC)      Wp = (const float*)d_in[i];
    }
    float* out = (float*)d_out;

    cudaFuncSetAttribute(attn_kernel,
                         cudaFuncAttributeMaxDynamicSharedMemorySize,
                         ATTN_SMEM);

    // 1) QKV projection: [4096,2304] = x @ W_attn^T, scattered into q/k/v
    gemm_nt<0><<<dim3(3 * NC / 128, NB * NT / 128), 256>>>(x, Wa, nullptr, NC, 3 * NC);

    // 2) Causal flash attention -> g_y [b,t,c]
    attn_kernel<<<dim3(NT / 128, NB * NH), 128, ATTN_SMEM>>>();

    // 3) Output projection: out = g_y @ W_proj^T
    gemm_nt<1><<<dim3(NC / 128, NB * NT / 128), 256>>>(nullptr, Wp, out, NC, NC);
}

// round 6
// speedup vs baseline: 4.0620x; 4.0620x over previous
#include <cuda_runtime.h>
#include <cuda_bf16.h>
#include <math.h>

#define NB 2
#define NT 2048
#define NC 768
#define NH 12
#define ND 64

// Scratch (allocation-free rule: device globals)
__device__ float g_q[NB*NH*NT*ND];   // [b][h][t][d]
__device__ float g_k[NB*NH*NT*ND];
__device__ float g_v[NB*NH*NT*ND];
__device__ float g_y[NB*NT*NC];      // [b][t][c]

// ---------------------------------------------------------------------------
// helpers
// ---------------------------------------------------------------------------
__device__ __forceinline__ unsigned f2tf32(float x) {
    unsigned r;
    asm("cvt.rna.tf32.f32 %0, %1;" : "=r"(r) : "f"(x));
    return r;
}

__device__ __forceinline__ unsigned short bfbits(__nv_bfloat16 h) {
    return *reinterpret_cast<unsigned short*>(&h);
}

// D += A*B, m16n8k8 tf32
__device__ __forceinline__ void mma_tf32(float c[4], const unsigned a[4],
                                         unsigned b0, unsigned b1) {
    asm volatile(
        "mma.sync.aligned.m16n8k8.row.col.f32.tf32.tf32.f32 "
        "{%0,%1,%2,%3},{%4,%5,%6,%7},{%8,%9},{%0,%1,%2,%3};\n"
        : "+f"(c[0]), "+f"(c[1]), "+f"(c[2]), "+f"(c[3])
        : "r"(a[0]), "r"(a[1]), "r"(a[2]), "r"(a[3]), "r"(b0), "r"(b1));
}

// D += A*B, m16n8k16 bf16
__device__ __forceinline__ void mma_bf16(float c[4], const unsigned a[4],
                                         unsigned b0, unsigned b1) {
    asm volatile(
        "mma.sync.aligned.m16n8k16.row.col.f32.bf16.bf16.f32 "
        "{%0,%1,%2,%3},{%4,%5,%6,%7},{%8,%9},{%0,%1,%2,%3};\n"
        : "+f"(c[0]), "+f"(c[1]), "+f"(c[2]), "+f"(c[3])
        : "r"(a[0]), "r"(a[1]), "r"(a[2]), "r"(a[3]), "r"(b0), "r"(b1));
}

// ---------------------------------------------------------------------------
// 3xBF16 NT GEMM: C[m,n] = sum_k A[m,k]*B[n,k], near-fp32 accuracy.
// BM=128, BN=64, BK=32, 256 threads = 8 warps (4m x 2n), warp tile 32x32.
// MODE 0: A=x, scatter epilogue into g_q/g_k/g_v   MODE 1: A=g_y, plain write
// ---------------------------------------------------------------------------
__device__ __forceinline__ void scat_qkv(int m, int n, float v0, float v1) {
    int b = m >> 11;
    int t = m & 2047;
    int which = n / NC;
    int r = n - which * NC;
    int h = r >> 6;
    int d = r & 63;
    float* dst = (which == 0) ? g_q : (which == 1) ? g_k : g_v;
    *(float2*)(dst + (((size_t)b * NH + h) * NT + t) * ND + d) = make_float2(v0, v1);
}

template<int MODE>
__global__ void __launch_bounds__(256, 2)
gemm3bf(const float* __restrict__ Aext, const float* __restrict__ Bw,
        float* __restrict__ Cout, int K, int N)
{
    const float* A = (MODE == 0) ? Aext : g_y;

    // bf16 smem, padded stride 40 (conflict-free for frag pattern 20g+t)
    __shared__ __align__(16) unsigned short AsH[128 * 40];
    __shared__ __align__(16) unsigned short AsL[128 * 40];
    __shared__ __align__(16) unsigned short BsH[64 * 40];
    __shared__ __align__(16) unsigned short BsL[64 * 40];

    const int m0 = blockIdx.y * 128;
    const int n0 = blockIdx.x * 64;
    const int tid = threadIdx.x;
    const int wid = tid >> 5, lane = tid & 31;
    const int g = lane >> 2, t = lane & 3;
    const int wm = wid >> 1, wn = wid & 1;

    float acc[2][4][4];
    #pragma unroll
    for (int mt = 0; mt < 2; mt++)
        #pragma unroll
        for (int nt = 0; nt < 4; nt++)
            #pragma unroll
            for (int i = 0; i < 4; i++) acc[mt][nt][i] = 0.0f;

    for (int k0 = 0; k0 < K; k0 += 32) {
        // ---- load A tile 128x32 (4 float4/thread), split hi/lo bf16 ----
        #pragma unroll
        for (int i = 0; i < 4; i++) {
            int idx = tid + i * 256;
            int row = idx >> 3, c4 = (idx & 7) << 2;
            float4 v = *(const float4*)(A + (size_t)(m0 + row) * K + k0 + c4);
            __nv_bfloat16 hx = __float2bfloat16_rn(v.x);
            __nv_bfloat16 hy = __float2bfloat16_rn(v.y);
            __nv_bfloat16 hz = __float2bfloat16_rn(v.z);
            __nv_bfloat16 hw = __float2bfloat16_rn(v.w);
            __nv_bfloat16 lx = __float2bfloat16_rn(v.x - __bfloat162float(hx));
            __nv_bfloat16 ly = __float2bfloat16_rn(v.y - __bfloat162float(hy));
            __nv_bfloat16 lz = __float2bfloat16_rn(v.z - __bfloat162float(hz));
            __nv_bfloat16 lw = __float2bfloat16_rn(v.w - __bfloat162float(hw));
            unsigned h01 = ((unsigned)bfbits(hy) << 16) | bfbits(hx);
            unsigned h23 = ((unsigned)bfbits(hw) << 16) | bfbits(hz);
            unsigned l01 = ((unsigned)bfbits(ly) << 16) | bfbits(lx);
            unsigned l23 = ((unsigned)bfbits(lw) << 16) | bfbits(lz);
            *(uint2*)(AsH + row * 40 + c4) = make_uint2(h01, h23);
            *(uint2*)(AsL + row * 40 + c4) = make_uint2(l01, l23);
        }
        // ---- load B tile 64x32 (2 float4/thread) ----
        #pragma unroll
        for (int i = 0; i < 2; i++) {
            int idx = tid + i * 256;
            int row = idx >> 3, c4 = (idx & 7) << 2;
            float4 v = *(const float4*)(Bw + (size_t)(n0 + row) * K + k0 + c4);
            __nv_bfloat16 hx = __float2bfloat16_rn(v.x);
            __nv_bfloat16 hy = __float2bfloat16_rn(v.y);
            __nv_bfloat16 hz = __float2bfloat16_rn(v.z);
            __nv_bfloat16 hw = __float2bfloat16_rn(v.w);
            __nv_bfloat16 lx = __float2bfloat16_rn(v.x - __bfloat162float(hx));
            __nv_bfloat16 ly = __float2bfloat16_rn(v.y - __bfloat162float(hy));
            __nv_bfloat16 lz = __float2bfloat16_rn(v.z - __bfloat162float(hz));
            __nv_bfloat16 lw = __float2bfloat16_rn(v.w - __bfloat162float(hw));
            unsigned h01 = ((unsigned)bfbits(hy) << 16) | bfbits(hx);
            unsigned h23 = ((unsigned)bfbits(hw) << 16) | bfbits(hz);
            unsigned l01 = ((unsigned)bfbits(ly) << 16) | bfbits(lx);
            unsigned l23 = ((unsigned)bfbits(lw) << 16) | bfbits(lz);
            *(uint2*)(BsH + row * 40 + c4) = make_uint2(h01, h23);
            *(uint2*)(BsL + row * 40 + c4) = make_uint2(l01, l23);
        }
        __syncthreads();

        #pragma unroll
        for (int ks = 0; ks < 2; ks++) {
            const int ko = ks * 16;
            unsigned aH[2][4], aL[2][4], bH[4][2], bL[4][2];
            #pragma unroll
            for (int mt = 0; mt < 2; mt++) {
                int r = wm * 32 + mt * 16 + g;
                int b0o = r * 40 + ko + 2 * t;
                int b1o = (r + 8) * 40 + ko + 2 * t;
                aH[mt][0] = *(const unsigned*)(AsH + b0o);
                aH[mt][1] = *(const unsigned*)(AsH + b1o);
                aH[mt][2] = *(const unsigned*)(AsH + b0o + 8);
                aH[mt][3] = *(const unsigned*)(AsH + b1o + 8);
                aL[mt][0] = *(const unsigned*)(AsL + b0o);
                aL[mt][1] = *(const unsigned*)(AsL + b1o);
                aL[mt][2] = *(const unsigned*)(AsL + b0o + 8);
                aL[mt][3] = *(const unsigned*)(AsL + b1o + 8);
            }
            #pragma unroll
            for (int nt = 0; nt < 4; nt++) {
                int r = wn * 32 + nt * 8 + g;
                int bo = r * 40 + ko + 2 * t;
                bH[nt][0] = *(const unsigned*)(BsH + bo);
                bH[nt][1] = *(const unsigned*)(BsH + bo + 8);
                bL[nt][0] = *(const unsigned*)(BsL + bo);
                bL[nt][1] = *(const unsigned*)(BsL + bo + 8);
            }
            #pragma unroll
            for (int mt = 0; mt < 2; mt++)
                #pragma unroll
                for (int nt = 0; nt < 4; nt++) {
                    mma_bf16(acc[mt][nt], aH[mt], bH[nt][0], bH[nt][1]);
                    mma_bf16(acc[mt][nt], aH[mt], bL[nt][0], bL[nt][1]);
                    mma_bf16(acc[mt][nt], aL[mt], bH[nt][0], bH[nt][1]);
                }
        }
        __syncthreads();
    }

    // ---- epilogue ----
    #pragma unroll
    for (int mt = 0; mt < 2; mt++) {
        int r0 = m0 + wm * 32 + mt * 16 + g;
        int r1 = r0 + 8;
        #pragma unroll
        for (int nt = 0; nt < 4; nt++) {
            int c = n0 + wn * 32 + nt * 8 + 2 * t;
            if (MODE == 0) {
                scat_qkv(r0, c, acc[mt][nt][0], acc[mt][nt][1]);
                scat_qkv(r1, c, acc[mt][nt][2], acc[mt][nt][3]);
            } else {
                *(float2*)(Cout + (size_t)r0 * N + c) =
                    make_float2(acc[mt][nt][0], acc[mt][nt][1]);
                *(float2*)(Cout + (size_t)r1 * N + c) =
                    make_float2(acc[mt][nt][2], acc[mt][nt][3]);
            }
        }
    }
}

// ---------------------------------------------------------------------------
// Flash attention with tf32 mma.sync.
// 256 threads = 8 warps; Q tile 128 rows (16 per warp); K/V tile 64.
// Per warp: S (16x64) = Q(16x64)@K^T, softmax (2 rows/thread, shfl over t),
// P->smem (tf32), O(16x64) += P@V.  smem strides: Q/K/P 68, V 72 (conflict-free).
// ---------------------------------------------------------------------------
#define Q_U (128 * 68)
#define K_U (64 * 68)
#define V_U (64 * 72)
#define P_U (128 * 68)
#define ATTN_SMEM ((Q_U + K_U + V_U + P_U) * 4)

__global__ void __launch_bounds__(256, 2) attn_mma()
{
    extern __shared__ __align__(16) unsigned su[];
    unsigned* Qs = su;
    unsigned* Ks = su + Q_U;
    unsigned* Vs = Ks + K_U;
    unsigned* Ps = Vs + V_U;

    const int qt = (int)gridDim.x - 1 - (int)blockIdx.x;   // heavy blocks first
    const int bh = blockIdx.y;
    const int b = bh / NH;
    const int h = bh - b * NH;
    const int tid = threadIdx.x;
    const int wid = tid >> 5, lane = tid & 31;
    const int g = lane >> 2, t = lane & 3;
    const int R = wid * 16;

    const size_t head_base = ((size_t)b * NH + h) * (size_t)NT * ND;
    const int q0 = qt * 128;

    // load Q tile -> tf32
    {
        const float* qg = g_q + head_base + (size_t)q0 * ND;
        #pragma unroll
        for (int i = 0; i < 8; i++) {
            int idx = tid + i * 256;             // 2048 float4
            int row = idx >> 4, d4 = (idx & 15) << 2;
            float4 v = *(const float4*)(qg + row * ND + d4);
            uint4 u = make_uint4(f2tf32(v.x), f2tf32(v.y), f2tf32(v.z), f2tf32(v.w));
            *(uint4*)(Qs + row * 68 + d4) = u;
        }
    }

    float mrow[2] = {-1e30f, -1e30f};
    float lrow[2] = {0.0f, 0.0f};
    float o[8][4];
    #pragma unroll
    for (int nt = 0; nt < 8; nt++)
        #pragma unroll
        for (int i = 0; i < 4; i++) o[nt][i] = 0.0f;

    const int kt_max = 2 * qt + 1;
    for (int kt = 0; kt <= kt_max; kt++) {
        const int k0 = kt * 64;

        __syncthreads();  // prior readers of Ks/Vs/Ps done (covers Q load on iter 0)
        {
            const float* kg = g_k + head_base + (size_t)k0 * ND;
            const float* vg = g_v + head_base + (size_t)k0 * ND;
            #pragma unroll
            for (int i = 0; i < 4; i++) {
                int idx = tid + i * 256;         // 1024 float4 per tensor
                int row = idx >> 4, d4 = (idx & 15) << 2;
                float4 v = *(const float4*)(kg + row * ND + d4);
                *(uint4*)(Ks + row * 68 + d4) =
                    make_uint4(f2tf32(v.x), f2tf32(v.y), f2tf32(v.z), f2tf32(v.w));
                float4 w = *(const float4*)(vg + row * ND + d4);
                *(uint4*)(Vs + row * 72 + d4) =
                    make_uint4(f2tf32(w.x), f2tf32(w.y), f2tf32(w.z), f2tf32(w.w));
            }
        }
        __syncthreads();

        // ---- S = Q K^T ----
        float sc[8][4];
        #pragma unroll
        for (int nt = 0; nt < 8; nt++)
            #pragma unroll
            for (int i = 0; i < 4; i++) sc[nt][i] = 0.0f;

        #pragma unroll
        for (int ks = 0; ks < 8; ks++) {
            unsigned a[4];
            int ra = (R + g) * 68 + ks * 8 + t;
            int rb = (R + g + 8) * 68 + ks * 8 + t;
            a[0] = Qs[ra];
            a[1] = Qs[rb];
            a[2] = Qs[ra + 4];
            a[3] = Qs[rb + 4];
            #pragma unroll
            for (int nt = 0; nt < 8; nt++) {
                int kb = (nt * 8 + g) * 68 + ks * 8 + t;
                mma_tf32(sc[nt], a, Ks[kb], Ks[kb + 4]);
            }
        }

        // ---- scale + causal mask ----
        const bool nm = (kt >= 2 * qt);
        const int rlo = q0 + R + g;
        const int rhi = rlo + 8;
        #pragma unroll
        for (int nt = 0; nt < 8; nt++) {
            int cc = k0 + nt * 8 + 2 * t;
            sc[nt][0] *= 0.125f;
            sc[nt][1] *= 0.125f;
            sc[nt][2] *= 0.125f;
            sc[nt][3] *= 0.125f;
            if (nm) {
                if (cc > rlo)     sc[nt][0] = -1e30f;
                if (cc + 1 > rlo) sc[nt][1] = -1e30f;
                if (cc > rhi)     sc[nt][2] = -1e30f;
                if (cc + 1 > rhi) sc[nt][3] = -1e30f;
            }
        }

        // ---- online softmax (rows owned by 4-lane groups; reduce over t) ----
        float mx0 = -1e30f, mx1 = -1e30f;
        #pragma unroll
        for (int nt = 0; nt < 8; nt++) {
            mx0 = fmaxf(mx0, fmaxf(sc[nt][0], sc[nt][1]));
            mx1 = fmaxf(mx1, fmaxf(sc[nt][2], sc[nt][3]));
        }
        mx0 = fmaxf(mx0, __shfl_xor_sync(0xffffffffu, mx0, 1));
        mx0 = fmaxf(mx0, __shfl_xor_sync(0xffffffffu, mx0, 2));
        mx1 = fmaxf(mx1, __shfl_xor_sync(0xffffffffu, mx1, 1));
        mx1 = fmaxf(mx1, __shfl_xor_sync(0xffffffffu, mx1, 2));

        float mn0 = fmaxf(mrow[0], mx0);
        float mn1 = fmaxf(mrow[1], mx1);
        float al0 = __expf(mrow[0] - mn0);
        float al1 = __expf(mrow[1] - mn1);
        mrow[0] = mn0;
        mrow[1] = mn1;

        float rs0 = 0.0f, rs1 = 0.0f;
        #pragma unroll
        for (int nt = 0; nt < 8; nt++) {
            sc[nt][0] = __expf(sc[nt][0] - mn0); rs0 += sc[nt][0];
            sc[nt][1] = __expf(sc[nt][1] - mn0); rs0 += sc[nt][1];
            sc[nt][2] = __expf(sc[nt][2] - mn1); rs1 += sc[nt][2];
            sc[nt][3] = __expf(sc[nt][3] - mn1); rs1 += sc[nt][3];
        }
        rs0 += __shfl_xor_sync(0xffffffffu, rs0, 1);
        rs0 += __shfl_xor_sync(0xffffffffu, rs0, 2);
        rs1 += __shfl_xor_sync(0xffffffffu, rs1, 1);
        rs1 += __shfl_xor_sync(0xffffffffu, rs1, 2);
        lrow[0] = lrow[0] * al0 + rs0;
        lrow[1] = lrow[1] * al1 + rs1;

        #pragma unroll
        for (int nt = 0; nt < 8; nt++) {
            o[nt][0] *= al0; o[nt][1] *= al0;
            o[nt][2] *= al1; o[nt][3] *= al1;
        }

        // ---- P -> smem (tf32), own rows only ----
        #pragma unroll
        for (int nt = 0; nt < 8; nt++) {
            int pa = (R + g) * 68 + nt * 8 + 2 * t;
            int pb = (R + g + 8) * 68 + nt * 8 + 2 * t;
            *(uint2*)(Ps + pa) = make_uint2(f2tf32(sc[nt][0]), f2tf32(sc[nt][1]));
            *(uint2*)(Ps + pb) = make_uint2(f2tf32(sc[nt][2]), f2tf32(sc[nt][3]));
        }
        __syncwarp();

        // ---- O += P V ----
        #pragma unroll
        for (int ks = 0; ks < 8; ks++) {
            unsigned a[4];
            int ra = (R + g) * 68 + ks * 8 + t;
            int rb = (R + g + 8) * 68 + ks * 8 + t;
            a[0] = Ps[ra];
            a[1] = Ps[rb];
            a[2] = Ps[ra + 4];
            a[3] = Ps[rb + 4];
            #pragma unroll
            for (int nt = 0; nt < 8; nt++) {
                int v0 = (ks * 8 + t) * 72 + nt * 8 + g;
                int v1 = (ks * 8 + t + 4) * 72 + nt * 8 + g;
                mma_tf32(o[nt], a, Vs[v0], Vs[v1]);
            }
        }
    }

    // ---- epilogue: normalize, write [b,t,c] ----
    float i0 = 1.0f / lrow[0];
    float i1 = 1.0f / lrow[1];
    float* y0 = g_y + ((size_t)b * NT + (q0 + R + g)) * NC + h * ND;
    float* y1 = g_y + ((size_t)b * NT + (q0 + R + g + 8)) * NC + h * ND;
    #pragma unroll
    for (int nt = 0; nt < 8; nt++) {
        *(float2*)(y0 + nt * 8 + 2 * t) = make_float2(o[nt][0] * i0, o[nt][1] * i0);
        *(float2*)(y1 + nt * 8 + 2 * t) = make_float2(o[nt][2] * i1, o[nt][3] * i1);
    }
}

// ---------------------------------------------------------------------------
extern "C" void kernel_launch(void* const* d_in, const int* in_sizes, int n_in,
                              void* d_out, int out_size)
{
    const float* x  = nullptr;   // 3145728
    const float* Wa = nullptr;   // 1769472
    const float* Wp = nullptr;   // 589824
    for (int i = 0; i < n_in; i++) {
        if (in_sizes[i] == NB * NT * NC)      x  = (const float*)d_in[i];
        else if (in_sizes[i] == 3 * NC * NC)  Wa = (const float*)d_in[i];
        else if (in_sizes[i] == NC * NC)      Wp = (const float*)d_in[i];
    }
    float* out = (float*)d_out;

    cudaFuncSetAttribute(attn_mma,
                         cudaFuncAttributeMaxDynamicSharedMemorySize,
                         ATTN_SMEM);

    // 1) QKV projection (3xBF16 tensor cores), scatter into q/k/v
    gemm3bf<0><<<dim3(3 * NC / 64, NB * NT / 128), 256>>>(x, Wa, nullptr, NC, 3 * NC);

    // 2) Causal flash attention (tf32 tensor cores) -> g_y [b,t,c]
    attn_mma<<<dim3(NT / 128, NB * NH), 256, ATTN_SMEM>>>();

    // 3) Output projection (3xBF16 tensor cores)
    gemm3bf<1><<<dim3(NC / 64, NB * NT / 128), 256>>>(nullptr, Wp, out, NC, NC);
}

// round 8
// speedup vs baseline: 4.2287x; 1.0410x over previous
#include <cuda_runtime.h>
#include <cuda_bf16.h>
#include <math.h>
#include <stdint.h>

#define NB 2
#define NT 2048
#define NC 768
#define NH 12
#define ND 64

// ---------------------------------------------------------------------------
// Device-global scratch (allocation-free rule)
// ---------------------------------------------------------------------------
__device__ float g_q[NB*NH*NT*ND];   // [b][h][t][d] fp32
__device__ float g_k[NB*NH*NT*ND];
__device__ float g_v[NB*NH*NT*ND];

__device__ __align__(16) __nv_bfloat16 g_xH[NB*NT*NC];
__device__ __align__(16) __nv_bfloat16 g_xL[NB*NT*NC];
__device__ __align__(16) __nv_bfloat16 g_waH[3*NC*NC];
__device__ __align__(16) __nv_bfloat16 g_waL[3*NC*NC];
__device__ __align__(16) __nv_bfloat16 g_wpH[NC*NC];
__device__ __align__(16) __nv_bfloat16 g_wpL[NC*NC];
__device__ __align__(16) __nv_bfloat16 g_yH[NB*NT*NC];
__device__ __align__(16) __nv_bfloat16 g_yL[NB*NT*NC];

// ---------------------------------------------------------------------------
// helpers
// ---------------------------------------------------------------------------
__device__ __forceinline__ uint32_t smem_to_u32(const void* p) {
    uint32_t a;
    asm("{ .reg .u64 t; cvta.to.shared.u64 t, %1; cvt.u32.u64 %0, t; }"
        : "=r"(a) : "l"(p));
    return a;
}

__device__ __forceinline__ void cp_async16(uint32_t saddr, const void* gptr) {
    asm volatile("cp.async.cg.shared.global [%0], [%1], 16;"
                 :: "r"(saddr), "l"(gptr) : "memory");
}
__device__ __forceinline__ void cp_commit() {
    asm volatile("cp.async.commit_group;" ::: "memory");
}
__device__ __forceinline__ void cp_wait0() {
    asm volatile("cp.async.wait_group 0;" ::: "memory");
}

__device__ __forceinline__ unsigned f2tf32(float x) {
    unsigned r;
    asm("cvt.rna.tf32.f32 %0, %1;" : "=r"(r) : "f"(x));
    return r;
}

// D += A*B, m16n8k8 tf32
__device__ __forceinline__ void mma_tf32(float c[4], const unsigned a[4],
                                         unsigned b0, unsigned b1) {
    asm volatile(
        "mma.sync.aligned.m16n8k8.row.col.f32.tf32.tf32.f32 "
        "{%0,%1,%2,%3},{%4,%5,%6,%7},{%8,%9},{%0,%1,%2,%3};\n"
        : "+f"(c[0]), "+f"(c[1]), "+f"(c[2]), "+f"(c[3])
        : "r"(a[0]), "r"(a[1]), "r"(a[2]), "r"(a[3]), "r"(b0), "r"(b1));
}

// D += A*B, m16n8k16 bf16
__device__ __forceinline__ void mma_bf16(float c[4], const unsigned a[4],
                                         unsigned b0, unsigned b1) {
    asm volatile(
        "mma.sync.aligned.m16n8k16.row.col.f32.bf16.bf16.f32 "
        "{%0,%1,%2,%3},{%4,%5,%6,%7},{%8,%9},{%0,%1,%2,%3};\n"
        : "+f"(c[0]), "+f"(c[1]), "+f"(c[2]), "+f"(c[3])
        : "r"(a[0]), "r"(a[1]), "r"(a[2]), "r"(a[3]), "r"(b0), "r"(b1));
}

// ---------------------------------------------------------------------------
// Split fp32 -> (bf16 hi, bf16 lo). which: 0=x, 1=Wa, 2=Wp
// ---------------------------------------------------------------------------
__global__ void split_bf(const float* __restrict__ s, int which) {
    __nv_bfloat16 *dH, *dL;
    if (which == 0)      { dH = g_xH;  dL = g_xL;  }
    else if (which == 1) { dH = g_waH; dL = g_waL; }
    else                 { dH = g_wpH; dL = g_wpL; }
    int i4 = (blockIdx.x * 256 + threadIdx.x) * 4;
    float4 v = *(const float4*)(s + i4);
    __nv_bfloat16 h0 = __float2bfloat16_rn(v.x);
    __nv_bfloat16 h1 = __float2bfloat16_rn(v.y);
    __nv_bfloat16 h2 = __float2bfloat16_rn(v.z);
    __nv_bfloat16 h3 = __float2bfloat16_rn(v.w);
    ((__nv_bfloat162*)(dH + i4))[0] = __halves2bfloat162(h0, h1);
    ((__nv_bfloat162*)(dH + i4))[1] = __halves2bfloat162(h2, h3);
    ((__nv_bfloat162*)(dL + i4))[0] = __halves2bfloat162(
        __float2bfloat16_rn(v.x - __bfloat162float(h0)),
        __float2bfloat16_rn(v.y - __bfloat162float(h1)));
    ((__nv_bfloat162*)(dL + i4))[1] = __halves2bfloat162(
        __float2bfloat16_rn(v.z - __bfloat162float(h2)),
        __float2bfloat16_rn(v.w - __bfloat162float(h3)));
}

// ---------------------------------------------------------------------------
// 3xBF16 NT GEMM on mma.sync, pre-split bf16 inputs, cp.async double-buffered.
// BM=128, BN=64, BK=32, 256 threads = 8 warps (4m x 2n), warp tile 32x32.
// smem ushort layout (dynamic):
//   AH[2][128*40] | AL[2][128*40] | BH[2][64*40] | BL[2][64*40]
// MODE 0: scatter epilogue -> g_q/g_k/g_v    MODE 1: row-major -> Cout
// ---------------------------------------------------------------------------
#define A_STG (128 * 40)
#define B_STG (64 * 40)
#define U_AH 0
#define U_AL (2 * A_STG)
#define U_BH (4 * A_STG)
#define U_BL (4 * A_STG + 2 * B_STG)
#define GEMM_SMEM ((4 * A_STG + 4 * B_STG) * 2)   // bytes = 61440

__device__ __forceinline__ void scat_qkv(int m, int n, float v0, float v1) {
    int b = m >> 11;
    int t = m & 2047;
    int which = n / NC;
    int r = n - which * NC;
    int h = r >> 6;
    int d = r & 63;
    float* dst = (which == 0) ? g_q : (which == 1) ? g_k : g_v;
    *(float2*)(dst + (((size_t)b * NH + h) * NT + t) * ND + d) = make_float2(v0, v1);
}

template<int MODE>
__global__ void __launch_bounds__(256, 2)
gemm3bf(float* __restrict__ Cout, int K, int N)
{
    extern __shared__ __align__(16) unsigned short us[];

    const __nv_bfloat16* AH = (MODE == 0) ? g_xH  : g_yH;
    const __nv_bfloat16* AL = (MODE == 0) ? g_xL  : g_yL;
    const __nv_bfloat16* BH = (MODE == 0) ? g_waH : g_wpH;
    const __nv_bfloat16* BL = (MODE == 0) ? g_waL : g_wpL;

    const uint32_t sb = smem_to_u32(us);
    const int m0 = blockIdx.y * 128;
    const int n0 = blockIdx.x * 64;
    const int tid = threadIdx.x;
    const int wid = tid >> 5, lane = tid & 31;
    const int g = lane >> 2, t = lane & 3;
    const int wm = wid >> 1, wn = wid & 1;

    // per-thread load coordinates
    const int arow0 = tid >> 2;            // A: 2 uint4 (rows tid>>2, +64)
    const int ac8   = (tid & 3) * 8;
    const int brow  = tid >> 2;            // B: 1 uint4 each
    const int bc8   = (tid & 3) * 8;

    auto load_stage = [&](int s, int k0) {
        // A tiles: 128x32 bf16 = 512 uint4 (2/thread per matrix)
        #pragma unroll
        for (int i = 0; i < 2; i++) {
            int row = arow0 + i * 64;
            uint32_t so = (uint32_t)(row * 40 + ac8) * 2;
            size_t ga = (size_t)(m0 + row) * K + k0 + ac8;
            cp_async16(sb + (U_AH + s * A_STG) * 2 + so, AH + ga);
            cp_async16(sb + (U_AL + s * A_STG) * 2 + so, AL + ga);
        }
        // B tiles: 64x32 bf16 = 256 uint4 (1/thread per matrix)
        {
            uint32_t so = (uint32_t)(brow * 40 + bc8) * 2;
            size_t gb = (size_t)(n0 + brow) * K + k0 + bc8;
            cp_async16(sb + (U_BH + s * B_STG) * 2 + so, BH + gb);
            cp_async16(sb + (U_BL + s * B_STG) * 2 + so, BL + gb);
        }
        cp_commit();
    };

    float acc[2][4][4];
    #pragma unroll
    for (int mt = 0; mt < 2; mt++)
        #pragma unroll
        for (int nt = 0; nt < 4; nt++)
            #pragma unroll
            for (int i = 0; i < 4; i++) acc[mt][nt][i] = 0.0f;

    const int NK = K / 32;
    load_stage(0, 0);

    for (int c = 0; c < NK; c++) {
        cp_wait0();
        __syncthreads();
        if (c + 1 < NK) load_stage((c + 1) & 1, (c + 1) * 32);

        const unsigned short* sAH = us + U_AH + (c & 1) * A_STG;
        const unsigned short* sAL = us + U_AL + (c & 1) * A_STG;
        const unsigned short* sBH = us + U_BH + (c & 1) * B_STG;
        const unsigned short* sBL = us + U_BL + (c & 1) * B_STG;

        #pragma unroll
        for (int ks = 0; ks < 2; ks++) {
            const int ko = ks * 16;
            unsigned aH[2][4], aL[2][4], bH[4][2], bL[4][2];
            #pragma unroll
            for (int mt = 0; mt < 2; mt++) {
                int r = wm * 32 + mt * 16 + g;
                int b0o = r * 40 + ko + 2 * t;
                int b1o = (r + 8) * 40 + ko + 2 * t;
                aH[mt][0] = *(const unsigned*)(sAH + b0o);
                aH[mt][1] = *(const unsigned*)(sAH + b1o);
                aH[mt][2] = *(const unsigned*)(sAH + b0o + 8);
                aH[mt][3] = *(const unsigned*)(sAH + b1o + 8);
                aL[mt][0] = *(const unsigned*)(sAL + b0o);
                aL[mt][1] = *(const unsigned*)(sAL + b1o);
                aL[mt][2] = *(const unsigned*)(sAL + b0o + 8);
                aL[mt][3] = *(const unsigned*)(sAL + b1o + 8);
            }
            #pragma unroll
            for (int nt = 0; nt < 4; nt++) {
                int r = wn * 32 + nt * 8 + g;
                int bo = r * 40 + ko + 2 * t;
                bH[nt][0] = *(const unsigned*)(sBH + bo);
                bH[nt][1] = *(const unsigned*)(sBH + bo + 8);
                bL[nt][0] = *(const unsigned*)(sBL + bo);
                bL[nt][1] = *(const unsigned*)(sBL + bo + 8);
            }
            #pragma unroll
            for (int mt = 0; mt < 2; mt++)
                #pragma unroll
                for (int nt = 0; nt < 4; nt++) {
                    mma_bf16(acc[mt][nt], aH[mt], bH[nt][0], bH[nt][1]);
                    mma_bf16(acc[mt][nt], aH[mt], bL[nt][0], bL[nt][1]);
                    mma_bf16(acc[mt][nt], aL[mt], bH[nt][0], bH[nt][1]);
                }
        }
        __syncthreads();
    }

    // ---- epilogue ----
    #pragma unroll
    for (int mt = 0; mt < 2; mt++) {
        int r0 = m0 + wm * 32 + mt * 16 + g;
        int r1 = r0 + 8;
        #pragma unroll
        for (int nt = 0; nt < 4; nt++) {
            int c = n0 + wn * 32 + nt * 8 + 2 * t;
            if (MODE == 0) {
                scat_qkv(r0, c, acc[mt][nt][0], acc[mt][nt][1]);
                scat_qkv(r1, c, acc[mt][nt][2], acc[mt][nt][3]);
            } else {
                *(float2*)(Cout + (size_t)r0 * N + c) =
                    make_float2(acc[mt][nt][0], acc[mt][nt][1]);
                *(float2*)(Cout + (size_t)r1 * N + c) =
                    make_float2(acc[mt][nt][2], acc[mt][nt][3]);
            }
        }
    }
}

// ---------------------------------------------------------------------------
// Flash attention, tf32 mma.sync (math identical to R6; epilogue -> yH/yL).
// 256 threads = 8 warps; Q tile 128 rows (16/warp); K/V tile 64.
// ---------------------------------------------------------------------------
#define Q_U (128 * 68)
#define K_U (64 * 68)
#define V_U (64 * 72)
#define P_U (128 * 68)
#define ATTN_SMEM ((Q_U + K_U + V_U + P_U) * 4)

__global__ void __launch_bounds__(256, 2) attn_mma()
{
    extern __shared__ __align__(16) unsigned su[];
    unsigned* Qs = su;
    unsigned* Ks = su + Q_U;
    unsigned* Vs = Ks + K_U;
    unsigned* Ps = Vs + V_U;

    const int qt = (int)gridDim.x - 1 - (int)blockIdx.x;
    const int bh = blockIdx.y;
    const int b = bh / NH;
    const int h = bh - b * NH;
    const int tid = threadIdx.x;
    const int wid = tid >> 5, lane = tid & 31;
    const int g = lane >> 2, t = lane & 3;
    const int R = wid * 16;

    const size_t head_base = ((size_t)b * NH + h) * (size_t)NT * ND;
    const int q0 = qt * 128;

    {
        const float* qg = g_q + head_base + (size_t)q0 * ND;
        #pragma unroll
        for (int i = 0; i < 8; i++) {
            int idx = tid + i * 256;
            int row = idx >> 4, d4 = (idx & 15) << 2;
            float4 v = *(const float4*)(qg + row * ND + d4);
            *(uint4*)(Qs + row * 68 + d4) =
                make_uint4(f2tf32(v.x), f2tf32(v.y), f2tf32(v.z), f2tf32(v.w));
        }
    }

    float mrow[2] = {-1e30f, -1e30f};
    float lrow[2] = {0.0f, 0.0f};
    float o[8][4];
    #pragma unroll
    for (int nt = 0; nt < 8; nt++)
        #pragma unroll
        for (int i = 0; i < 4; i++) o[nt][i] = 0.0f;

    const int kt_max = 2 * qt + 1;
    for (int kt = 0; kt <= kt_max; kt++) {
        const int k0 = kt * 64;

        __syncthreads();
        {
            const float* kg = g_k + head_base + (size_t)k0 * ND;
            const float* vg = g_v + head_base + (size_t)k0 * ND;
            #pragma unroll
            for (int i = 0; i < 4; i++) {
                int idx = tid + i * 256;
                int row = idx >> 4, d4 = (idx & 15) << 2;
                float4 v = *(const float4*)(kg + row * ND + d4);
                *(uint4*)(Ks + row * 68 + d4) =
                    make_uint4(f2tf32(v.x), f2tf32(v.y), f2tf32(v.z), f2tf32(v.w));
                float4 w = *(const float4*)(vg + row * ND + d4);
                *(uint4*)(Vs + row * 72 + d4) =
                    make_uint4(f2tf32(w.x), f2tf32(w.y), f2tf32(w.z), f2tf32(w.w));
            }
        }
        __syncthreads();

        float sc[8][4];
        #pragma unroll
        for (int nt = 0; nt < 8; nt++)
            #pragma unroll
            for (int i = 0; i < 4; i++) sc[nt][i] = 0.0f;

        #pragma unroll
        for (int ks = 0; ks < 8; ks++) {
            unsigned a[4];
            int ra = (R + g) * 68 + ks * 8 + t;
            int rb = (R + g + 8) * 68 + ks * 8 + t;
            a[0] = Qs[ra]; a[1] = Qs[rb]; a[2] = Qs[ra + 4]; a[3] = Qs[rb + 4];
            #pragma unroll
            for (int nt = 0; nt < 8; nt++) {
                int kb = (nt * 8 + g) * 68 + ks * 8 + t;
                mma_tf32(sc[nt], a, Ks[kb], Ks[kb + 4]);
            }
        }

        const bool nm = (kt >= 2 * qt);
        const int rlo = q0 + R + g;
        const int rhi = rlo + 8;
        #pragma unroll
        for (int nt = 0; nt < 8; nt++) {
            int cc = k0 + nt * 8 + 2 * t;
            sc[nt][0] *= 0.125f; sc[nt][1] *= 0.125f;
            sc[nt][2] *= 0.125f; sc[nt][3] *= 0.125f;
            if (nm) {
                if (cc > rlo)     sc[nt][0] = -1e30f;
                if (cc + 1 > rlo) sc[nt][1] = -1e30f;
                if (cc > rhi)     sc[nt][2] = -1e30f;
                if (cc + 1 > rhi) sc[nt][3] = -1e30f;
            }
        }

        float mx0 = -1e30f, mx1 = -1e30f;
        #pragma unroll
        for (int nt = 0; nt < 8; nt++) {
            mx0 = fmaxf(mx0, fmaxf(sc[nt][0], sc[nt][1]));
            mx1 = fmaxf(mx1, fmaxf(sc[nt][2], sc[nt][3]));
        }
        mx0 = fmaxf(mx0, __shfl_xor_sync(0xffffffffu, mx0, 1));
        mx0 = fmaxf(mx0, __shfl_xor_sync(0xffffffffu, mx0, 2));
        mx1 = fmaxf(mx1, __shfl_xor_sync(0xffffffffu, mx1, 1));
        mx1 = fmaxf(mx1, __shfl_xor_sync(0xffffffffu, mx1, 2));

        float mn0 = fmaxf(mrow[0], mx0);
        float mn1 = fmaxf(mrow[1], mx1);
        float al0 = __expf(mrow[0] - mn0);
        float al1 = __expf(mrow[1] - mn1);
        mrow[0] = mn0; mrow[1] = mn1;

        float rs0 = 0.0f, rs1 = 0.0f;
        #pragma unroll
        for (int nt = 0; nt < 8; nt++) {
            sc[nt][0] = __expf(sc[nt][0] - mn0); rs0 += sc[nt][0];
            sc[nt][1] = __expf(sc[nt][1] - mn0); rs0 += sc[nt][1];
            sc[nt][2] = __expf(sc[nt][2] - mn1); rs1 += sc[nt][2];
            sc[nt][3] = __expf(sc[nt][3] - mn1); rs1 += sc[nt][3];
        }
        rs0 += __shfl_xor_sync(0xffffffffu, rs0, 1);
        rs0 += __shfl_xor_sync(0xffffffffu, rs0, 2);
        rs1 += __shfl_xor_sync(0xffffffffu, rs1, 1);
        rs1 += __shfl_xor_sync(0xffffffffu, rs1, 2);
        lrow[0] = lrow[0] * al0 + rs0;
        lrow[1] = lrow[1] * al1 + rs1;

        #pragma unroll
        for (int nt = 0; nt < 8; nt++) {
            o[nt][0] *= al0; o[nt][1] *= al0;
            o[nt][2] *= al1; o[nt][3] *= al1;
        }

        #pragma unroll
        for (int nt = 0; nt < 8; nt++) {
            int pa = (R + g) * 68 + nt * 8 + 2 * t;
            int pb = (R + g + 8) * 68 + nt * 8 + 2 * t;
            *(uint2*)(Ps + pa) = make_uint2(f2tf32(sc[nt][0]), f2tf32(sc[nt][1]));
            *(uint2*)(Ps + pb) = make_uint2(f2tf32(sc[nt][2]), f2tf32(sc[nt][3]));
        }
        __syncwarp();

        #pragma unroll
        for (int ks = 0; ks < 8; ks++) {
            unsigned a[4];
            int ra = (R + g) * 68 + ks * 8 + t;
            int rb = (R + g + 8) * 68 + ks * 8 + t;
            a[0] = Ps[ra]; a[1] = Ps[rb]; a[2] = Ps[ra + 4]; a[3] = Ps[rb + 4];
            #pragma unroll
            for (int nt = 0; nt < 8; nt++) {
                int v0 = (ks * 8 + t) * 72 + nt * 8 + g;
                int v1 = (ks * 8 + t + 4) * 72 + nt * 8 + g;
                mma_tf32(o[nt], a, Vs[v0], Vs[v1]);
            }
        }
    }

    // epilogue: normalize; emit bf16 hi/lo directly for the proj GEMM
    float i0 = 1.0f / lrow[0];
    float i1 = 1.0f / lrow[1];
    size_t base0 = ((size_t)b * NT + (q0 + R + g)) * NC + h * ND;
    size_t base1 = ((size_t)b * NT + (q0 + R + g + 8)) * NC + h * ND;
    #pragma unroll
    for (int nt = 0; nt < 8; nt++) {
        size_t off0 = base0 + nt * 8 + 2 * t;
        size_t off1 = base1 + nt * 8 + 2 * t;
        float v0 = o[nt][0] * i0, v1 = o[nt][1] * i0;
        float v2 = o[nt][2] * i1, v3 = o[nt][3] * i1;
        __nv_bfloat16 h0 = __float2bfloat16_rn(v0);
        __nv_bfloat16 h1 = __float2bfloat16_rn(v1);
        __nv_bfloat16 h2 = __float2bfloat16_rn(v2);
        __nv_bfloat16 h3 = __float2bfloat16_rn(v3);
        *(__nv_bfloat162*)(g_yH + off0) = __halves2bfloat162(h0, h1);
        *(__nv_bfloat162*)(g_yH + off1) = __halves2bfloat162(h2, h3);
        *(__nv_bfloat162*)(g_yL + off0) = __halves2bfloat162(
            __float2bfloat16_rn(v0 - __bfloat162float(h0)),
            __float2bfloat16_rn(v1 - __bfloat162float(h1)));
        *(__nv_bfloat162*)(g_yL + off1) = __halves2bfloat162(
            __float2bfloat16_rn(v2 - __bfloat162float(h2)),
            __float2bfloat16_rn(v3 - __bfloat162float(h3)));
    }
}

// ---------------------------------------------------------------------------
extern "C" void kernel_launch(void* const* d_in, const int* in_sizes, int n_in,
                              void* d_out, int out_size)
{
    const float* x  = nullptr;   // 3145728
    const float* Wa = nullptr;   // 1769472
    const float* Wp = nullptr;   // 589824
    for (int i = 0; i < n_in; i++) {
        if (in_sizes[i] == NB * NT * NC)      x  = (const float*)d_in[i];
        else if (in_sizes[i] == 3 * NC * NC)  Wa = (const float*)d_in[i];
        else if (in_sizes[i] == NC * NC)      Wp = (const float*)d_in[i];
    }
    float* out = (float*)d_out;

    cudaFuncSetAttribute(attn_mma,
                         cudaFuncAttributeMaxDynamicSharedMemorySize, ATTN_SMEM);
    cudaFuncSetAttribute(gemm3bf<0>,
                         cudaFuncAttributeMaxDynamicSharedMemorySize, GEMM_SMEM);
    cudaFuncSetAttribute(gemm3bf<1>,
                         cudaFuncAttributeMaxDynamicSharedMemorySize, GEMM_SMEM);

    // 0) one-time hi/lo bf16 splits
    split_bf<<<(NB * NT * NC) / 1024, 256>>>(x, 0);
    split_bf<<<(3 * NC * NC) / 1024, 256>>>(Wa, 1);
    split_bf<<<(NC * NC) / 1024, 256>>>(Wp, 2);

    // 1) QKV projection (pre-split bf16, cp.async pipelined), scatter q/k/v
    gemm3bf<0><<<dim3(3 * NC / 64, NB * NT / 128), 256, GEMM_SMEM>>>(nullptr, NC, 3 * NC);

    // 2) causal flash attention (tf32 mma.sync) -> yH/yL bf16
    attn_mma<<<dim3(NT / 128, NB * NH), 256, ATTN_SMEM>>>();

    // 3) output projection
    gemm3bf<1><<<dim3(NC / 64, NB * NT / 128), 256, GEMM_SMEM>>>(out, NC, NC);
}